// round 14
// baseline (speedup 1.0000x reference)
#include <cuda_runtime.h>
#include <cuda_bf16.h>
#include <cstdint>
#include <math.h>

#define N_SPK 2048
#define M_UTT 16
#define D_EMB 512
#define NM (N_SPK * M_UTT)
#define EPSF 1e-8f
#define GRID_GEMM 152                  // GB300: 152 SMs, persistent 1 CTA/SM
#define NUNITS 2048                    // 256 mtiles x 8 ntiles

// ---------------- scratch (allocation-free rule: __device__ globals) -------
__device__ __nv_bfloat16 g_vnb[NM * D_EMB];     // normalized utterances, bf16
__device__ __nv_bfloat16 g_Cnb[N_SPK * D_EMB];  // normalized centroids,  bf16
__device__ float g_sdiag[NM];                   // cos(C_min[j], v_j) fp32-exact
__device__ float g_sself[NM];                   // dot of bf16-rounded Cn,vn
__device__ float g_colsum[NM];                  // sum_n exp(w*(S[n,j]-1))

// ---------------- helpers ---------------------------------------------------
__device__ __forceinline__ uint32_t smem_u32(const void* p) {
    uint32_t a;
    asm("{ .reg .u64 t; cvta.to.shared.u64 t, %1; cvt.u32.u64 %0, t; }" : "=r"(a) : "l"(p));
    return a;
}
__device__ __forceinline__ void cp16(uint32_t s, const void* g) {
    asm volatile("cp.async.cg.shared.global [%0], [%1], 16;" :: "r"(s), "l"(g) : "memory");
}
__device__ __forceinline__ void cp_commit() { asm volatile("cp.async.commit_group;" ::: "memory"); }
__device__ __forceinline__ void cp_wait1()  { asm volatile("cp.async.wait_group 1;" ::: "memory"); }
__device__ __forceinline__ float ex2a(float x) {
    float r; asm("ex2.approx.f32 %0, %1;" : "=f"(r) : "f"(x)); return r;
}
#define MMA_BF16(d, a0, a1, a2, a3, b0, b1)                                   \
    asm volatile(                                                             \
        "mma.sync.aligned.m16n8k16.row.col.f32.bf16.bf16.f32 "                \
        "{%0,%1,%2,%3}, {%4,%5,%6,%7}, {%8,%9}, {%0,%1,%2,%3};"               \
        : "+f"(d[0]), "+f"(d[1]), "+f"(d[2]), "+f"(d[3])                      \
        : "r"(a0), "r"(a1), "r"(a2), "r"(a3), "r"(b0), "r"(b1))
#define LDSM_X4(r0, r1, r2, r3, addr)                                         \
    asm volatile(                                                             \
        "ldmatrix.sync.aligned.m8n8.x4.shared.b16 {%0,%1,%2,%3}, [%4];"       \
        : "=r"(r0), "=r"(r1), "=r"(r2), "=r"(r3) : "r"(addr))

// ---------------- prep: registerized (no smem data buffer) ------------------
// Thread owns columns tid and tid+256 for all 16 rows: 32 floats in regs.
// Global loads fully coalesced; smem only for the 33-value block reduction.
__global__ __launch_bounds__(256) void prep_kernel(const float* __restrict__ v,
                                                   float* __restrict__ outp) {
    __shared__ float red[8][33];
    __shared__ float fin[33];

    const int tid = threadIdx.x;
    const int n = blockIdx.x;

    if (tid < 16) g_colsum[n * 16 + tid] = 0.0f;   // zero for gemm atomics
    if (n == 0 && tid == 0) *outp = 0.0f;          // zero for loss atomics

    float x0[M_UTT], x1[M_UTT];
    const float* src = v + (size_t)n * M_UTT * D_EMB;
    #pragma unroll
    for (int m = 0; m < M_UTT; m++) {
        x0[m] = src[m * D_EMB + tid];
        x1[m] = src[m * D_EMB + tid + 256];
    }

    float s0 = 0.0f, s1 = 0.0f;
    #pragma unroll
    for (int m = 0; m < M_UTT; m++) { s0 += x0[m]; s1 += x1[m]; }

    float vals[33];
    #pragma unroll
    for (int m = 0; m < M_UTT; m++) {
        vals[m]      = x0[m] * x0[m] + x1[m] * x1[m];   // ||v_m||^2 partial
        vals[16 + m] = s0 * x0[m] + s1 * x1[m];          // ssum.v_m partial
    }
    vals[32] = s0 * s0 + s1 * s1;                        // ||ssum||^2 partial

    #pragma unroll
    for (int i = 0; i < 33; i++) {
        float x = vals[i];
        #pragma unroll
        for (int o = 16; o > 0; o >>= 1) x += __shfl_xor_sync(0xffffffffu, x, o);
        vals[i] = x;
    }
    const int warp = tid >> 5, lane = tid & 31;
    if (lane == 0) {
        #pragma unroll
        for (int i = 0; i < 33; i++) red[warp][i] = vals[i];
    }
    __syncthreads();
    if (tid < 33) {
        float x = 0.0f;
        #pragma unroll
        for (int w = 0; w < 8; w++) x += red[w][tid];
        fin[tid] = x;
    }
    __syncthreads();

    const float ss = fin[32];
    const float cinv = 1.0f / fmaxf(sqrtf(ss), (float)M_UTT * EPSF);

    __nv_bfloat16 cb0 = __float2bfloat16(s0 * cinv);
    __nv_bfloat16 cb1 = __float2bfloat16(s1 * cinv);
    g_Cnb[n * D_EMB + tid]       = cb0;
    g_Cnb[n * D_EMB + tid + 256] = cb1;
    const float fc0 = __bfloat162float(cb0);
    const float fc1 = __bfloat162float(cb1);

    float sfp[M_UTT];
    #pragma unroll
    for (int m = 0; m < M_UTT; m++) {
        float rv = 1.0f / fmaxf(sqrtf(fin[m]), EPSF);
        __nv_bfloat16 vb0 = __float2bfloat16(x0[m] * rv);
        __nv_bfloat16 vb1 = __float2bfloat16(x1[m] * rv);
        size_t base = (size_t)(n * M_UTT + m) * D_EMB;
        g_vnb[base + tid]       = vb0;
        g_vnb[base + tid + 256] = vb1;
        sfp[m] = fc0 * __bfloat162float(vb0) + fc1 * __bfloat162float(vb1);
    }

    // reduce sself (dot of rounded values == what the GEMM computes)
    #pragma unroll
    for (int m = 0; m < M_UTT; m++) {
        float x = sfp[m];
        #pragma unroll
        for (int o = 16; o > 0; o >>= 1) x += __shfl_xor_sync(0xffffffffu, x, o);
        sfp[m] = x;
    }
    if (lane == 0) {
        #pragma unroll
        for (int m = 0; m < M_UTT; m++) red[warp][m] = sfp[m];
    }
    __syncthreads();
    if (tid < M_UTT) {
        float x = 0.0f;
        #pragma unroll
        for (int w = 0; w < 8; w++) x += red[w][tid];
        g_sself[n * M_UTT + tid] = x;

        float sq  = fin[tid];
        float dsv = fin[16 + tid];
        float nv  = fmaxf(sqrtf(sq), EPSF);
        float cm2 = fmaxf(ss - 2.0f * dsv + sq, 0.0f);
        const float invMm1 = 1.0f / (float)(M_UTT - 1);
        float ncm = fmaxf(sqrtf(cm2) * invMm1, EPSF);
        g_sdiag[n * M_UTT + tid] = ((dsv - sq) * invMm1) / (ncm * nv);
    }
}

// ---------------- persistent GEMM + fused exp rowsum (R12, measured) --------
#define A_PITCHB 1040                      // bytes per A row (520 bf16)
#define B_PITCHB 144                       // bytes per B row (72 bf16)
#define SA_BYTES (128 * A_PITCHB)          // 133120
#define SB_BYTES (256 * B_PITCHB)          // 36864 per buffer
#define SB_OFF   SA_BYTES
#define SRED_OFF (SB_OFF + 2 * SB_BYTES)   // 206848
#define SMEM_SZ  (SRED_OFF + 4 * 128 * 4)  // 208896

__global__ __launch_bounds__(256, 1) void gemm_lse_kernel(const float* __restrict__ wp) {
    extern __shared__ char smem[];
    const uint32_t sbase = smem_u32(smem);
    float* red = (float*)(smem + SRED_OFF);

    const int tid = threadIdx.x;
    const int lane = tid & 31, wid = tid >> 5;
    const int warpM = wid & 1;
    const int warpN = wid >> 1;
    const int qg = lane >> 2, t = lane & 3;
    const int mat = lane >> 3, rr = lane & 7;

    const int start = (int)(((long long)blockIdx.x * NUNITS) / GRID_GEMM);
    const int end   = (int)(((long long)(blockIdx.x + 1) * NUNITS) / GRID_GEMM);

    const float wv = *wp;
    const float c1 = wv * 1.44269504f;
    const float c0 = -c1;

    uint32_t aAddr[4];
    #pragma unroll
    for (int i = 0; i < 4; i++)
        aAddr[i] = sbase + (uint32_t)(warpM * 64 + i * 16 + (mat & 1) * 8 + rr) * A_PITCHB
                 + (uint32_t)(mat >> 1) * 16;
    uint32_t bAddr[4];
    #pragma unroll
    for (int j2 = 0; j2 < 4; j2++)
        bAddr[j2] = sbase + SB_OFF
                  + (uint32_t)(warpN * 64 + j2 * 16 + (mat >> 1) * 8 + rr) * B_PITCHB
                  + (uint32_t)(mat & 1) * 16;

    auto loadB = [&](int ntile, int kc, int buf) {
        const __nv_bfloat16* bsrc = g_Cnb + (size_t)(ntile * 256) * D_EMB + kc * 64;
        const uint32_t bb = sbase + SB_OFF + buf * SB_BYTES;
        #pragma unroll
        for (int i = 0; i < 8; i++) {
            int flat = tid + 256 * i;
            int row = flat >> 3, k8 = flat & 7;
            cp16(bb + row * B_PITCHB + k8 * 16,
                 bsrc + (size_t)row * D_EMB + k8 * 8);
        }
    };

    float acc[4][8][4];
    #pragma unroll
    for (int i = 0; i < 4; i++)
        #pragma unroll
        for (int j = 0; j < 8; j++)
            #pragma unroll
            for (int r = 0; r < 4; r++) acc[i][j][r] = 0.0f;

    for (int g = start; g < end; ) {
        const int mt = g >> 3;
        const int run_end = min(end, (mt + 1) << 3);
        const int cnt = (run_end - g) * 8;

        {
            const __nv_bfloat16* vsrc = g_vnb + (size_t)(mt * 128) * D_EMB;
            #pragma unroll 8
            for (int i = 0; i < 32; i++) {
                int flat = tid + 256 * i;
                int row = flat >> 6, cc = flat & 63;
                cp16(sbase + row * A_PITCHB + cc * 16,
                     vsrc + (size_t)row * D_EMB + cc * 8);
            }
        }
        loadB(g & 7, 0, 0); cp_commit();
        loadB(g & 7, 1, 1); cp_commit();

        float rs[4][2] = {{0,0},{0,0},{0,0},{0,0}};

        #pragma unroll 1
        for (int c = 0; c < cnt; c++) {
            const int buf = c & 1;
            cp_wait1();
            __syncthreads();

            const uint32_t kcB = (uint32_t)(c & 7) * 128;
            const uint32_t bOff = (uint32_t)buf * SB_BYTES;

            uint32_t ra[2][4][4], rb[2][4][4];
            #pragma unroll
            for (int i = 0; i < 4; i++)
                LDSM_X4(ra[0][i][0], ra[0][i][1], ra[0][i][2], ra[0][i][3],
                        aAddr[i] + kcB);
            #pragma unroll
            for (int j2 = 0; j2 < 4; j2++)
                LDSM_X4(rb[0][j2][0], rb[0][j2][1], rb[0][j2][2], rb[0][j2][3],
                        bAddr[j2] + bOff);

            #pragma unroll
            for (int s = 0; s < 4; s++) {
                const int cur = s & 1, nxt = cur ^ 1;
                if (s < 3) {
                    #pragma unroll
                    for (int i = 0; i < 4; i++)
                        LDSM_X4(ra[nxt][i][0], ra[nxt][i][1], ra[nxt][i][2], ra[nxt][i][3],
                                aAddr[i] + kcB + (s + 1) * 32);
                    #pragma unroll
                    for (int j2 = 0; j2 < 4; j2++)
                        LDSM_X4(rb[nxt][j2][0], rb[nxt][j2][1], rb[nxt][j2][2], rb[nxt][j2][3],
                                bAddr[j2] + bOff + (s + 1) * 32);
                }
                #pragma unroll
                for (int j2 = 0; j2 < 4; j2++)
                    #pragma unroll
                    for (int i = 0; i < 4; i++) {
                        MMA_BF16(acc[i][2 * j2],
                                 ra[cur][i][0], ra[cur][i][1], ra[cur][i][2], ra[cur][i][3],
                                 rb[cur][j2][0], rb[cur][j2][1]);
                        MMA_BF16(acc[i][2 * j2 + 1],
                                 ra[cur][i][0], ra[cur][i][1], ra[cur][i][2], ra[cur][i][3],
                                 rb[cur][j2][2], rb[cur][j2][3]);
                    }
            }

            __syncthreads();
            if (c + 2 < cnt) {
                const int c2 = c + 2;
                loadB((g + (c2 >> 3)) & 7, c2 & 7, buf);
            }
            cp_commit();

            if ((c & 7) == 7) {
                #pragma unroll
                for (int i = 0; i < 4; i++) {
                    float a0 = 0.0f, a1 = 0.0f;
                    #pragma unroll
                    for (int j = 0; j < 8; j++) {
                        a0 += ex2a(fmaf(acc[i][j][0], c1, c0)) + ex2a(fmaf(acc[i][j][1], c1, c0));
                        a1 += ex2a(fmaf(acc[i][j][2], c1, c0)) + ex2a(fmaf(acc[i][j][3], c1, c0));
                        acc[i][j][0] = acc[i][j][1] = acc[i][j][2] = acc[i][j][3] = 0.0f;
                    }
                    rs[i][0] += a0;
                    rs[i][1] += a1;
                }
            }
        }

        #pragma unroll
        for (int i = 0; i < 4; i++)
            #pragma unroll
            for (int r = 0; r < 2; r++) {
                float x = rs[i][r];
                x += __shfl_xor_sync(0xffffffffu, x, 1);
                x += __shfl_xor_sync(0xffffffffu, x, 2);
                rs[i][r] = x;
            }
        if (t == 0) {
            #pragma unroll
            for (int i = 0; i < 4; i++)
                #pragma unroll
                for (int r = 0; r < 2; r++)
                    red[warpN * 128 + warpM * 64 + i * 16 + r * 8 + qg] = rs[i][r];
        }
        __syncthreads();
        if (tid < 128)
            atomicAdd(&g_colsum[mt * 128 + tid],
                      (red[tid] + red[128 + tid]) + (red[256 + tid] + red[384 + tid]));
        __syncthreads();

        g = run_end;
    }
}

// ---------------- final loss ------------------------------------------------
__global__ __launch_bounds__(256) void loss_kernel(const float* __restrict__ wp,
                                                   float* __restrict__ out) {
    __shared__ float rsm[8];
    const int j = blockIdx.x * blockDim.x + threadIdx.x;
    const float wv = *wp;
    const float c1 = wv * 1.44269504f;
    const float c0 = -c1;
    float L = 0.0f;
    if (j < NM) {
        float sd = g_sdiag[j];
        float sf = g_sself[j];
        float cs = g_colsum[j] - ex2a(fmaf(sf, c1, c0)) + ex2a(fmaf(sd, c1, c0));
        L = wv * (1.0f - sd) + logf(cs);
    }
    #pragma unroll
    for (int o = 16; o > 0; o >>= 1) L += __shfl_xor_sync(0xffffffffu, L, o);
    const int warp = threadIdx.x >> 5, lane = threadIdx.x & 31;
    if (lane == 0) rsm[warp] = L;
    __syncthreads();
    if (threadIdx.x == 0) {
        float tacc = 0.0f;
        #pragma unroll
        for (int w = 0; w < 8; w++) tacc += rsm[w];
        atomicAdd(out, tacc);
    }
}

// ---------------------------------------------------------------------------
extern "C" void kernel_launch(void* const* d_in, const int* in_sizes, int n_in,
                              void* d_out, int out_size) {
    const float* v  = (const float*)d_in[0];   // [NM, D] fp32
    const float* wp = (const float*)d_in[1];   // scalar w (b cancels analytically)
    float* out = (float*)d_out;

    cudaFuncSetAttribute(gemm_lse_kernel,
                         cudaFuncAttributeMaxDynamicSharedMemorySize, SMEM_SZ);

    prep_kernel<<<N_SPK, 256>>>(v, out);
    gemm_lse_kernel<<<GRID_GEMM, 256, SMEM_SZ>>>(wp);
    loss_kernel<<<NM / 256, 256>>>(wp, out);
}

// round 15
// speedup vs baseline: 1.0170x; 1.0170x over previous
#include <cuda_runtime.h>
#include <cuda_bf16.h>
#include <cstdint>
#include <math.h>

#define N_SPK 2048
#define M_UTT 16
#define D_EMB 512
#define NM (N_SPK * M_UTT)
#define EPSF 1e-8f
#define GRID_GEMM 152                  // GB300: 152 SMs, persistent 1 CTA/SM
#define NUNITS 2048                    // 256 mtiles x 8 ntiles

// ---------------- scratch (allocation-free rule: __device__ globals) -------
__device__ __nv_bfloat16 g_vnb[NM * D_EMB];     // normalized utterances, bf16
__device__ __nv_bfloat16 g_Cnb[N_SPK * D_EMB];  // normalized centroids,  bf16
__device__ float g_sdiag[NM];                   // cos(C_min[j], v_j) fp32-exact
__device__ float g_sself[NM];                   // dot of bf16-rounded Cn,vn
__device__ float g_colsum[NM];                  // sum_n exp(w*(S[n,j]-1))

// ---------------- helpers ---------------------------------------------------
__device__ __forceinline__ uint32_t smem_u32(const void* p) {
    uint32_t a;
    asm("{ .reg .u64 t; cvta.to.shared.u64 t, %1; cvt.u32.u64 %0, t; }" : "=r"(a) : "l"(p));
    return a;
}
__device__ __forceinline__ void cp16(uint32_t s, const void* g) {
    asm volatile("cp.async.cg.shared.global [%0], [%1], 16;" :: "r"(s), "l"(g) : "memory");
}
__device__ __forceinline__ void cp_commit() { asm volatile("cp.async.commit_group;" ::: "memory"); }
__device__ __forceinline__ void cp_wait1()  { asm volatile("cp.async.wait_group 1;" ::: "memory"); }
__device__ __forceinline__ float ex2a(float x) {
    float r; asm("ex2.approx.f32 %0, %1;" : "=f"(r) : "f"(x)); return r;
}
#define MMA_BF16(d, a0, a1, a2, a3, b0, b1)                                   \
    asm volatile(                                                             \
        "mma.sync.aligned.m16n8k16.row.col.f32.bf16.bf16.f32 "                \
        "{%0,%1,%2,%3}, {%4,%5,%6,%7}, {%8,%9}, {%0,%1,%2,%3};"               \
        : "+f"(d[0]), "+f"(d[1]), "+f"(d[2]), "+f"(d[3])                      \
        : "r"(a0), "r"(a1), "r"(a2), "r"(a3), "r"(b0), "r"(b1))
#define LDSM_X4(r0, r1, r2, r3, addr)                                         \
    asm volatile(                                                             \
        "ldmatrix.sync.aligned.m8n8.x4.shared.b16 {%0,%1,%2,%3}, [%4];"       \
        : "=r"(r0), "=r"(r1), "=r"(r2), "=r"(r3) : "r"(addr))

// ---------------- prep: smem-tree reductions (no shfl trees) ----------------
// Thread owns columns tid, tid+256 for all 16 rows (32 regs). The 33 block
// reductions go through a 256x36 smem matrix with a float4 row tree:
// ~330 MIO warp-ops/block vs ~1320 for the shfl version.
__global__ __launch_bounds__(256) void prep_kernel(const float* __restrict__ v,
                                                   float* __restrict__ outp) {
    __shared__ float S[256][36];       // 36 KB; pitch 36 floats -> LDS.128 conflict-free
    __shared__ float fin[33];

    const int tid = threadIdx.x;
    const int n = blockIdx.x;

    if (tid < 16) g_colsum[n * 16 + tid] = 0.0f;   // zero for gemm atomics
    if (n == 0 && tid == 0) *outp = 0.0f;          // zero for loss atomics

    float x0[M_UTT], x1[M_UTT];
    const float* src = v + (size_t)n * M_UTT * D_EMB;
    #pragma unroll
    for (int m = 0; m < M_UTT; m++) {
        x0[m] = src[m * D_EMB + tid];
        x1[m] = src[m * D_EMB + tid + 256];
    }

    float s0 = 0.0f, s1 = 0.0f;
    #pragma unroll
    for (int m = 0; m < M_UTT; m++) { s0 += x0[m]; s1 += x1[m]; }

    // stage 33 partials: cols 0-15 sq, 16-31 dsv, 32 ss (33-35 zero)
    {
        float4* row = (float4*)&S[tid][0];
        #pragma unroll
        for (int m = 0; m < 16; m += 4) {
            float4 q;
            q.x = x0[m]     * x0[m]     + x1[m]     * x1[m];
            q.y = x0[m + 1] * x0[m + 1] + x1[m + 1] * x1[m + 1];
            q.z = x0[m + 2] * x0[m + 2] + x1[m + 2] * x1[m + 2];
            q.w = x0[m + 3] * x0[m + 3] + x1[m + 3] * x1[m + 3];
            row[m / 4] = q;
        }
        #pragma unroll
        for (int m = 0; m < 16; m += 4) {
            float4 q;
            q.x = s0 * x0[m]     + s1 * x1[m];
            q.y = s0 * x0[m + 1] + s1 * x1[m + 1];
            q.z = s0 * x0[m + 2] + s1 * x1[m + 2];
            q.w = s0 * x0[m + 3] + s1 * x1[m + 3];
            row[4 + m / 4] = q;
        }
        row[8] = make_float4(s0 * s0 + s1 * s1, 0.0f, 0.0f, 0.0f);
    }

    // float4 row tree: 256 -> 1
    #pragma unroll
    for (int st = 128; st >= 1; st >>= 1) {
        __syncthreads();
        if (tid < st) {
            float4* a = (float4*)&S[tid][0];
            const float4* b = (const float4*)&S[tid + st][0];
            #pragma unroll
            for (int k = 0; k < 9; k++) {
                float4 va = a[k], vb = b[k];
                va.x += vb.x; va.y += vb.y; va.z += vb.z; va.w += vb.w;
                a[k] = va;
            }
        }
    }
    __syncthreads();
    if (tid < 33) fin[tid] = S[0][tid];
    __syncthreads();                                   // fin ready; S reusable

    const float ss = fin[32];
    const float cinv = 1.0f / fmaxf(sqrtf(ss), (float)M_UTT * EPSF);

    __nv_bfloat16 cb0 = __float2bfloat16(s0 * cinv);
    __nv_bfloat16 cb1 = __float2bfloat16(s1 * cinv);
    g_Cnb[n * D_EMB + tid]       = cb0;
    g_Cnb[n * D_EMB + tid + 256] = cb1;
    const float fc0 = __bfloat162float(cb0);
    const float fc1 = __bfloat162float(cb1);

    float sfl[M_UTT];
    #pragma unroll
    for (int m = 0; m < M_UTT; m++) {
        float rv = 1.0f / fmaxf(sqrtf(fin[m]), EPSF);
        __nv_bfloat16 vb0 = __float2bfloat16(x0[m] * rv);
        __nv_bfloat16 vb1 = __float2bfloat16(x1[m] * rv);
        size_t base = (size_t)(n * M_UTT + m) * D_EMB;
        g_vnb[base + tid]       = vb0;
        g_vnb[base + tid + 256] = vb1;
        sfl[m] = fc0 * __bfloat162float(vb0) + fc1 * __bfloat162float(vb1);
    }

    // stage sself partials (cols 0-15) and tree-reduce
    {
        float4* row = (float4*)&S[tid][0];
        #pragma unroll
        for (int m = 0; m < 16; m += 4)
            row[m / 4] = make_float4(sfl[m], sfl[m + 1], sfl[m + 2], sfl[m + 3]);
    }
    #pragma unroll
    for (int st = 128; st >= 1; st >>= 1) {
        __syncthreads();
        if (tid < st) {
            float4* a = (float4*)&S[tid][0];
            const float4* b = (const float4*)&S[tid + st][0];
            #pragma unroll
            for (int k = 0; k < 4; k++) {
                float4 va = a[k], vb = b[k];
                va.x += vb.x; va.y += vb.y; va.z += vb.z; va.w += vb.w;
                a[k] = va;
            }
        }
    }
    __syncthreads();
    if (tid < M_UTT) {
        g_sself[n * M_UTT + tid] = S[0][tid];

        float sq  = fin[tid];
        float dsv = fin[16 + tid];
        float nv  = fmaxf(sqrtf(sq), EPSF);
        float cm2 = fmaxf(ss - 2.0f * dsv + sq, 0.0f);
        const float invMm1 = 1.0f / (float)(M_UTT - 1);
        float ncm = fmaxf(sqrtf(cm2) * invMm1, EPSF);
        g_sdiag[n * M_UTT + tid] = ((dsv - sq) * invMm1) / (ncm * nv);
    }
}

// ---------------- persistent GEMM + fused exp rowsum (R12, measured) --------
#define A_PITCHB 1040                      // bytes per A row (520 bf16)
#define B_PITCHB 144                       // bytes per B row (72 bf16)
#define SA_BYTES (128 * A_PITCHB)          // 133120
#define SB_BYTES (256 * B_PITCHB)          // 36864 per buffer
#define SB_OFF   SA_BYTES
#define SRED_OFF (SB_OFF + 2 * SB_BYTES)   // 206848
#define SMEM_SZ  (SRED_OFF + 4 * 128 * 4)  // 208896

__global__ __launch_bounds__(256, 1) void gemm_lse_kernel(const float* __restrict__ wp) {
    extern __shared__ char smem[];
    const uint32_t sbase = smem_u32(smem);
    float* red = (float*)(smem + SRED_OFF);

    const int tid = threadIdx.x;
    const int lane = tid & 31, wid = tid >> 5;
    const int warpM = wid & 1;
    const int warpN = wid >> 1;
    const int qg = lane >> 2, t = lane & 3;
    const int mat = lane >> 3, rr = lane & 7;

    const int start = (int)(((long long)blockIdx.x * NUNITS) / GRID_GEMM);
    const int end   = (int)(((long long)(blockIdx.x + 1) * NUNITS) / GRID_GEMM);

    const float wv = *wp;
    const float c1 = wv * 1.44269504f;
    const float c0 = -c1;

    uint32_t aAddr[4];
    #pragma unroll
    for (int i = 0; i < 4; i++)
        aAddr[i] = sbase + (uint32_t)(warpM * 64 + i * 16 + (mat & 1) * 8 + rr) * A_PITCHB
                 + (uint32_t)(mat >> 1) * 16;
    uint32_t bAddr[4];
    #pragma unroll
    for (int j2 = 0; j2 < 4; j2++)
        bAddr[j2] = sbase + SB_OFF
                  + (uint32_t)(warpN * 64 + j2 * 16 + (mat >> 1) * 8 + rr) * B_PITCHB
                  + (uint32_t)(mat & 1) * 16;

    auto loadB = [&](int ntile, int kc, int buf) {
        const __nv_bfloat16* bsrc = g_Cnb + (size_t)(ntile * 256) * D_EMB + kc * 64;
        const uint32_t bb = sbase + SB_OFF + buf * SB_BYTES;
        #pragma unroll
        for (int i = 0; i < 8; i++) {
            int flat = tid + 256 * i;
            int row = flat >> 3, k8 = flat & 7;
            cp16(bb + row * B_PITCHB + k8 * 16,
                 bsrc + (size_t)row * D_EMB + k8 * 8);
        }
    };

    float acc[4][8][4];
    #pragma unroll
    for (int i = 0; i < 4; i++)
        #pragma unroll
        for (int j = 0; j < 8; j++)
            #pragma unroll
            for (int r = 0; r < 4; r++) acc[i][j][r] = 0.0f;

    for (int g = start; g < end; ) {
        const int mt = g >> 3;
        const int run_end = min(end, (mt + 1) << 3);
        const int cnt = (run_end - g) * 8;

        {
            const __nv_bfloat16* vsrc = g_vnb + (size_t)(mt * 128) * D_EMB;
            #pragma unroll 8
            for (int i = 0; i < 32; i++) {
                int flat = tid + 256 * i;
                int row = flat >> 6, cc = flat & 63;
                cp16(sbase + row * A_PITCHB + cc * 16,
                     vsrc + (size_t)row * D_EMB + cc * 8);
            }
        }
        loadB(g & 7, 0, 0); cp_commit();
        loadB(g & 7, 1, 1); cp_commit();

        float rs[4][2] = {{0,0},{0,0},{0,0},{0,0}};

        #pragma unroll 1
        for (int c = 0; c < cnt; c++) {
            const int buf = c & 1;
            cp_wait1();
            __syncthreads();

            const uint32_t kcB = (uint32_t)(c & 7) * 128;
            const uint32_t bOff = (uint32_t)buf * SB_BYTES;

            uint32_t ra[2][4][4], rb[2][4][4];
            #pragma unroll
            for (int i = 0; i < 4; i++)
                LDSM_X4(ra[0][i][0], ra[0][i][1], ra[0][i][2], ra[0][i][3],
                        aAddr[i] + kcB);
            #pragma unroll
            for (int j2 = 0; j2 < 4; j2++)
                LDSM_X4(rb[0][j2][0], rb[0][j2][1], rb[0][j2][2], rb[0][j2][3],
                        bAddr[j2] + bOff);

            #pragma unroll
            for (int s = 0; s < 4; s++) {
                const int cur = s & 1, nxt = cur ^ 1;
                if (s < 3) {
                    #pragma unroll
                    for (int i = 0; i < 4; i++)
                        LDSM_X4(ra[nxt][i][0], ra[nxt][i][1], ra[nxt][i][2], ra[nxt][i][3],
                                aAddr[i] + kcB + (s + 1) * 32);
                    #pragma unroll
                    for (int j2 = 0; j2 < 4; j2++)
                        LDSM_X4(rb[nxt][j2][0], rb[nxt][j2][1], rb[nxt][j2][2], rb[nxt][j2][3],
                                bAddr[j2] + bOff + (s + 1) * 32);
                }
                #pragma unroll
                for (int j2 = 0; j2 < 4; j2++)
                    #pragma unroll
                    for (int i = 0; i < 4; i++) {
                        MMA_BF16(acc[i][2 * j2],
                                 ra[cur][i][0], ra[cur][i][1], ra[cur][i][2], ra[cur][i][3],
                                 rb[cur][j2][0], rb[cur][j2][1]);
                        MMA_BF16(acc[i][2 * j2 + 1],
                                 ra[cur][i][0], ra[cur][i][1], ra[cur][i][2], ra[cur][i][3],
                                 rb[cur][j2][2], rb[cur][j2][3]);
                    }
            }

            __syncthreads();
            if (c + 2 < cnt) {
                const int c2 = c + 2;
                loadB((g + (c2 >> 3)) & 7, c2 & 7, buf);
            }
            cp_commit();

            if ((c & 7) == 7) {
                #pragma unroll
                for (int i = 0; i < 4; i++) {
                    float a0 = 0.0f, a1 = 0.0f;
                    #pragma unroll
                    for (int j = 0; j < 8; j++) {
                        a0 += ex2a(fmaf(acc[i][j][0], c1, c0)) + ex2a(fmaf(acc[i][j][1], c1, c0));
                        a1 += ex2a(fmaf(acc[i][j][2], c1, c0)) + ex2a(fmaf(acc[i][j][3], c1, c0));
                        acc[i][j][0] = acc[i][j][1] = acc[i][j][2] = acc[i][j][3] = 0.0f;
                    }
                    rs[i][0] += a0;
                    rs[i][1] += a1;
                }
            }
        }

        #pragma unroll
        for (int i = 0; i < 4; i++)
            #pragma unroll
            for (int r = 0; r < 2; r++) {
                float x = rs[i][r];
                x += __shfl_xor_sync(0xffffffffu, x, 1);
                x += __shfl_xor_sync(0xffffffffu, x, 2);
                rs[i][r] = x;
            }
        if (t == 0) {
            #pragma unroll
            for (int i = 0; i < 4; i++)
                #pragma unroll
                for (int r = 0; r < 2; r++)
                    red[warpN * 128 + warpM * 64 + i * 16 + r * 8 + qg] = rs[i][r];
        }
        __syncthreads();
        if (tid < 128)
            atomicAdd(&g_colsum[mt * 128 + tid],
                      (red[tid] + red[128 + tid]) + (red[256 + tid] + red[384 + tid]));
        __syncthreads();

        g = run_end;
    }
}

// ---------------- final loss ------------------------------------------------
__global__ __launch_bounds__(256) void loss_kernel(const float* __restrict__ wp,
                                                   float* __restrict__ out) {
    __shared__ float rsm[8];
    const int j = blockIdx.x * blockDim.x + threadIdx.x;
    const float wv = *wp;
    const float c1 = wv * 1.44269504f;
    const float c0 = -c1;
    float L = 0.0f;
    if (j < NM) {
        float sd = g_sdiag[j];
        float sf = g_sself[j];
        float cs = g_colsum[j] - ex2a(fmaf(sf, c1, c0)) + ex2a(fmaf(sd, c1, c0));
        L = wv * (1.0f - sd) + logf(cs);
    }
    #pragma unroll
    for (int o = 16; o > 0; o >>= 1) L += __shfl_xor_sync(0xffffffffu, L, o);
    const int warp = threadIdx.x >> 5, lane = threadIdx.x & 31;
    if (lane == 0) rsm[warp] = L;
    __syncthreads();
    if (threadIdx.x == 0) {
        float tacc = 0.0f;
        #pragma unroll
        for (int w = 0; w < 8; w++) tacc += rsm[w];
        atomicAdd(out, tacc);
    }
}

// ---------------------------------------------------------------------------
extern "C" void kernel_launch(void* const* d_in, const int* in_sizes, int n_in,
                              void* d_out, int out_size) {
    const float* v  = (const float*)d_in[0];   // [NM, D] fp32
    const float* wp = (const float*)d_in[1];   // scalar w (b cancels analytically)
    float* out = (float*)d_out;

    cudaFuncSetAttribute(gemm_lse_kernel,
                         cudaFuncAttributeMaxDynamicSharedMemorySize, SMEM_SZ);

    prep_kernel<<<N_SPK, 256>>>(v, out);
    gemm_lse_kernel<<<GRID_GEMM, 256, SMEM_SZ>>>(wp);
    loss_kernel<<<NM / 256, 256>>>(wp, out);
}